// round 7
// baseline (speedup 1.0000x reference)
#include <cuda_runtime.h>
#include <math.h>

#define NH 4
#define NN 1024
#define EE 4096
#define NLE 16384
#define FN 128
#define FE 64
#define FNO 128
#define FEO 64
#define NODE_OUT_SZ (NH*NN*FNO)   /* 524288 */

// ---------------- scratch (device globals; zero-initialized at load) ----------------
__device__ float g_nv[NN*NH*FN];
__device__ float g_ev[EE*NH*FE];
__device__ float g_nk[NN*NH];          // flat k-linear output [row][c]
__device__ float g_ek[EE*NH];
__device__ float g_yn[NH*512];         // y[h][q], q=b*128+f   (atomics; zeroed each run)
__device__ float g_ye[NH*256];
__device__ float g_ksn[NH*4];          // ks[h][b]             (atomics; zeroed each run)
__device__ float g_kse[NH*4];
__device__ float g_un[NH*512];         // u[h][p], p=b*128+j
__device__ float g_ue[NH*256];
__device__ float g_cn[NH*4];           // c[h][b]
__device__ float g_ce[NH*4];
__device__ float g_nsa[NH*NN];
__device__ float g_esa[NH*EE];
__device__ int   g_cnt_n[NN], g_fc_n[NN], g_off_n[NN+1], g_lst_n[EE];
__device__ int   g_cnt_e[EE], g_fc_e[EE], g_off_e[EE+1], g_lst_e[NLE];
__device__ float g_ncWT[FNO*FN];
__device__ float g_ecWT[FEO*FE];
__device__ float g_WT4n[512*FN];       // WT4n[b*128+j][f] = nqW[(b*128+f)*128+j]
__device__ float g_WT4e[256*FE];       // WT4e[b*64+j][f]  = eqW[(b*64+f)*64+j]
__device__ float g_Rn[512*512];        // Gram: WT4n . WT4n^T
__device__ float g_Re[256*256];
__device__ float g_Sn[4*512];          // S'[b'][q] = sum_f nqb[b'*128+f]*WT4n[q][f]
__device__ float g_Se[4*256];
__device__ float g_zeros[512];         // never written: zero bias for Gram gemms

__device__ __forceinline__ float wredsum(float v)
{
#pragma unroll
    for (int o = 16; o; o >>= 1) v += __shfl_xor_sync(0xffffffffu, v, o);
    return v;
}

// ---------------- shared gemm tile:  C[M,N] = A[M,K] @ W[N,K]^T + b ----------------
__device__ __forceinline__
void gemm_tile(const float* __restrict__ A, const float* __restrict__ W,
               const float* __restrict__ bias, float* __restrict__ C,
               int bm, int bn, int Nout, int K)
{
    __shared__ float As[32][64];
    __shared__ float Bs[32][64];
    int tid = threadIdx.x;
    int tx = tid & 15, ty = tid >> 4;

    float acc[4][4];
#pragma unroll
    for (int i = 0; i < 4; i++)
#pragma unroll
        for (int j = 0; j < 4; j++) acc[i][j] = 0.f;

    for (int k0 = 0; k0 < K; k0 += 32) {
#pragma unroll
        for (int j = 0; j < 2; j++) {
            int f4 = tid + j * 256;
            int m  = f4 >> 3;
            int k4 = f4 & 7;
            float4 va = *reinterpret_cast<const float4*>(&A[(size_t)(bm + m) * K + k0 + k4 * 4]);
            As[k4*4+0][m] = va.x; As[k4*4+1][m] = va.y; As[k4*4+2][m] = va.z; As[k4*4+3][m] = va.w;
            float4 vb = *reinterpret_cast<const float4*>(&W[(size_t)(bn + m) * K + k0 + k4 * 4]);
            Bs[k4*4+0][m] = vb.x; Bs[k4*4+1][m] = vb.y; Bs[k4*4+2][m] = vb.z; Bs[k4*4+3][m] = vb.w;
        }
        __syncthreads();
#pragma unroll
        for (int kk = 0; kk < 32; kk++) {
            float4 a = *reinterpret_cast<const float4*>(&As[kk][ty * 4]);
            float4 b = *reinterpret_cast<const float4*>(&Bs[kk][tx * 4]);
            float ra[4] = {a.x, a.y, a.z, a.w};
            float rb[4] = {b.x, b.y, b.z, b.w};
#pragma unroll
            for (int i = 0; i < 4; i++)
#pragma unroll
                for (int j = 0; j < 4; j++) acc[i][j] += ra[i] * rb[j];
        }
        __syncthreads();
    }
#pragma unroll
    for (int i = 0; i < 4; i++) {
        int row = bm + ty * 4 + i;
        int col = bn + tx * 4;
        float4 r;
        r.x = acc[i][0] + bias[col+0];
        r.y = acc[i][1] + bias[col+1];
        r.z = acc[i][2] + bias[col+2];
        r.w = acc[i][3] + bias[col+3];
        *reinterpret_cast<float4*>(&C[(size_t)row * Nout + col]) = r;
    }
}

// ---------------- W1: prep + V gemms (single first wave) ----------------
// grid 1504 x 256: [0,640) k-proj warps, [640,720) counts, [720,1120) transposes, [1120,1504) V gemms
__global__ __launch_bounds__(256)
void prep_kernel(const float* __restrict__ node_in, const float* __restrict__ edge_in,
                 const float* __restrict__ nkW, const float* __restrict__ nkb,
                 const float* __restrict__ ekW, const float* __restrict__ ekb,
                 const int* __restrict__ src, const int* __restrict__ lg_src,
                 const float* __restrict__ ncW, const float* __restrict__ ecW,
                 const float* __restrict__ nqW, const float* __restrict__ eqW,
                 const float* __restrict__ nvW, const float* __restrict__ nvb,
                 const float* __restrict__ evW, const float* __restrict__ evb)
{
    int bid = blockIdx.x, tid = threadIdx.x;
    if (bid < 640) {
        int w = bid * 8 + (tid >> 5), lane = tid & 31;
        if (w < NN) {
            float4 xv = reinterpret_cast<const float4*>(node_in + w * FN)[lane];
            float4 w0 = reinterpret_cast<const float4*>(nkW + 0*FN)[lane];
            float4 w1 = reinterpret_cast<const float4*>(nkW + 1*FN)[lane];
            float4 w2 = reinterpret_cast<const float4*>(nkW + 2*FN)[lane];
            float4 w3 = reinterpret_cast<const float4*>(nkW + 3*FN)[lane];
            float p0 = xv.x*w0.x + xv.y*w0.y + xv.z*w0.z + xv.w*w0.w;
            float p1 = xv.x*w1.x + xv.y*w1.y + xv.z*w1.z + xv.w*w1.w;
            float p2 = xv.x*w2.x + xv.y*w2.y + xv.z*w2.z + xv.w*w2.w;
            float p3 = xv.x*w3.x + xv.y*w3.y + xv.z*w3.z + xv.w*w3.w;
            p0 = wredsum(p0); p1 = wredsum(p1); p2 = wredsum(p2); p3 = wredsum(p3);
            if (lane < 4) {
                float v = (lane == 0) ? p0 : (lane == 1) ? p1 : (lane == 2) ? p2 : p3;
                g_nk[w * 4 + lane] = v + nkb[lane];
            }
        } else {
            int row = w - NN;
            float2 xv = reinterpret_cast<const float2*>(edge_in + row * FE)[lane];
            float2 w0 = reinterpret_cast<const float2*>(ekW + 0*FE)[lane];
            float2 w1 = reinterpret_cast<const float2*>(ekW + 1*FE)[lane];
            float2 w2 = reinterpret_cast<const float2*>(ekW + 2*FE)[lane];
            float2 w3 = reinterpret_cast<const float2*>(ekW + 3*FE)[lane];
            float p0 = xv.x*w0.x + xv.y*w0.y;
            float p1 = xv.x*w1.x + xv.y*w1.y;
            float p2 = xv.x*w2.x + xv.y*w2.y;
            float p3 = xv.x*w3.x + xv.y*w3.y;
            p0 = wredsum(p0); p1 = wredsum(p1); p2 = wredsum(p2); p3 = wredsum(p3);
            if (lane < 4) {
                float v = (lane == 0) ? p0 : (lane == 1) ? p1 : (lane == 2) ? p2 : p3;
                g_ek[row * 4 + lane] = v + ekb[lane];
            }
        }
    } else if (bid < 720) {
        int idx = (bid - 640) * 256 + tid;
        if (idx < EE)            atomicAdd(&g_cnt_n[src[idx]], 1);
        else if (idx < EE + NLE) atomicAdd(&g_cnt_e[lg_src[idx - EE]], 1);
    } else if (bid < 1120) {
        int idx = (bid - 720) * 256 + tid;     // 0..102399
        if (idx < FNO*FN) {
            int o = idx >> 7, f = idx & 127;
            g_ncWT[f*FNO + o] = ncW[idx];
        } else if (idx < FNO*FN + FEO*FE) {
            int i = idx - FNO*FN;
            int o = i >> 6, f = i & 63;
            g_ecWT[f*FEO + o] = ecW[i];
        } else if (idx < FNO*FN + FEO*FE + 512*FN) {
            int i = idx - (FNO*FN + FEO*FE);
            int o = i >> 7, j = i & 127;       // nqW row o = b*128+f
            int b = o >> 7, f = o & 127;
            g_WT4n[(b*128 + j)*FN + f] = nqW[i];
        } else {
            int i = idx - (FNO*FN + FEO*FE + 512*FN);
            int o = i >> 6, j = i & 63;        // eqW row o = b*64+f
            int b = o >> 6, f = o & 63;
            g_WT4e[(b*64 + j)*FE + f] = eqW[i];
        }
    } else {
        int b = bid - 1120;
        if (b < 128) {
            gemm_tile(node_in, nvW, nvb, g_nv, (b >> 3) * 64, (b & 7) * 64, NH*FN, FN);
        } else {
            b -= 128;
            gemm_tile(edge_in, evW, evb, g_ev, (b >> 2) * 64, (b & 3) * 64, NH*FE, FE);
        }
    }
}

// ---------------- W2: scans + y/ks + Gram gemms + S' ----------------
__device__ void scan256(const int* __restrict__ in, int* __restrict__ out, int items)
{
    __shared__ int sums[256];
    int tid = threadIdx.x;
    int loc[16];
    int s = 0;
    for (int j = 0; j < items; j++) { loc[j] = in[tid * items + j]; s += loc[j]; }
    sums[tid] = s;
    __syncthreads();
    for (int off = 1; off < 256; off <<= 1) {
        int add = (tid >= off) ? sums[tid - off] : 0;
        __syncthreads();
        sums[tid] += add;
        __syncthreads();
    }
    int run = (tid == 0) ? 0 : sums[tid - 1];
    for (int j = 0; j < items; j++) { out[tid * items + j] = run; run += loc[j]; }
    if (tid == 255) out[256 * items] = sums[255];
}

// grid 626 x 256: 0 node-scan, 1 edge-scan, [2,34) node-y, [34,162) edge-y,
//                 [162,242) Gram tiles (64 node + 16 edge), [242,626) S' warps
__global__ __launch_bounds__(256)
void scan_y_gram_kernel(const float* __restrict__ node_in, const float* __restrict__ edge_in,
                        const float* __restrict__ nqb, const float* __restrict__ eqb)
{
    int bid = blockIdx.x, tid = threadIdx.x;
    if (bid == 0)      { scan256(g_cnt_n, g_off_n, 4); return; }
    else if (bid == 1) { scan256(g_cnt_e, g_off_e, 16); return; }
    else if (bid < 34) {
        // node-y: 32 rows per block; f = tid&127, part = tid>>7 (16 rows each)
        int blk = bid - 2;
        int h = blk >> 3;
        int f = tid & 127, part = tid >> 7;
        int m0 = blk * 32 + part * 16;
        float acc0 = 0.f, acc1 = 0.f, acc2 = 0.f, acc3 = 0.f;
        for (int m = m0; m < m0 + 16; m++) {
            float x = node_in[m * FN + f];
            const float* kp = g_nk + m * 4;
            acc0 += kp[0] * x; acc1 += kp[1] * x; acc2 += kp[2] * x; acc3 += kp[3] * x;
        }
        atomicAdd(&g_yn[h*512 + 0*FN + f], acc0);
        atomicAdd(&g_yn[h*512 + 1*FN + f], acc1);
        atomicAdd(&g_yn[h*512 + 2*FN + f], acc2);
        atomicAdd(&g_yn[h*512 + 3*FN + f], acc3);
        if (f < 4) {
            float s = 0.f;
            for (int m = m0; m < m0 + 16; m++) s += g_nk[m * 4 + f];
            atomicAdd(&g_ksn[h*4 + f], s);
        }
    } else if (bid < 162) {
        // edge-y: 32 rows per block; f = tid&63, part = tid>>6 (8 rows each)
        int blk = bid - 34;
        int h = blk >> 5;
        int f = tid & 63, part = tid >> 6;
        int m0 = blk * 32 + part * 8;
        float acc0 = 0.f, acc1 = 0.f, acc2 = 0.f, acc3 = 0.f;
        for (int m = m0; m < m0 + 8; m++) {
            float x = edge_in[m * FE + f];
            const float* kp = g_ek + m * 4;
            acc0 += kp[0] * x; acc1 += kp[1] * x; acc2 += kp[2] * x; acc3 += kp[3] * x;
        }
        atomicAdd(&g_ye[h*256 + 0*FE + f], acc0);
        atomicAdd(&g_ye[h*256 + 1*FE + f], acc1);
        atomicAdd(&g_ye[h*256 + 2*FE + f], acc2);
        atomicAdd(&g_ye[h*256 + 3*FE + f], acc3);
        if (f < 4) {
            float s = 0.f;
            for (int m = m0; m < m0 + 8; m++) s += g_ek[m * 4 + f];
            atomicAdd(&g_kse[h*4 + f], s);
        }
    } else if (bid < 242) {
        // Gram gemms: Rn = WT4n @ WT4n^T (64 tiles), Re = WT4e @ WT4e^T (16 tiles)
        int t = bid - 162;
        if (t < 64) gemm_tile(g_WT4n, g_WT4n, g_zeros, g_Rn, (t >> 3) * 64, (t & 7) * 64, 512, FN);
        else {
            int te = t - 64;
            gemm_tile(g_WT4e, g_WT4e, g_zeros, g_Re, (te >> 2) * 64, (te & 3) * 64, 256, FE);
        }
    } else {
        // S' warps: node 2048 then edge 1024
        int w = (bid - 242) * 8 + (tid >> 5), lane = tid & 31;
        if (w < 2048) {
            int bq = w >> 9, q = w & 511;
            float4 bb = *reinterpret_cast<const float4*>(&nqb[bq*FN + lane*4]);
            float4 wv = *reinterpret_cast<const float4*>(&g_WT4n[q*FN + lane*4]);
            float acc = bb.x*wv.x + bb.y*wv.y + bb.z*wv.z + bb.w*wv.w;
            acc = wredsum(acc);
            if (lane == 0) g_Sn[bq*512 + q] = acc;
        } else {
            int w2 = w - 2048;
            int bq = w2 >> 8, q = w2 & 255;
            float2 bb = *reinterpret_cast<const float2*>(&eqb[bq*FE + lane*2]);
            float2 wv = *reinterpret_cast<const float2*>(&g_WT4e[q*FE + lane*2]);
            float acc = bb.x*wv.x + bb.y*wv.y;
            acc = wredsum(acc);
            if (lane == 0) g_Se[bq*256 + q] = acc;
        }
    }
}

// ---------------- W3: CSR fill + u (via Gram) + c ----------------
// grid 468 x 256: [0,80) fill, [80,464) u warps (2048 node + 1024 edge), [464,468) c warps (32)
__global__ __launch_bounds__(256)
void fill_uc_kernel(const int* __restrict__ src, const int* __restrict__ lg_src,
                    const float* __restrict__ nqb, const float* __restrict__ eqb)
{
    int bid = blockIdx.x, tid = threadIdx.x;
    if (bid < 80) {
        int idx = bid * 256 + tid;
        if (idx < EE) {
            int s = src[idx];
            int p = g_off_n[s] + atomicAdd(&g_fc_n[s], 1);
            g_lst_n[p] = idx;
        } else if (idx < EE + NLE) {
            int l = idx - EE;
            int s = lg_src[l];
            int p = g_off_e[s] + atomicAdd(&g_fc_e[s], 1);
            g_lst_e[p] = l;
        }
        return;
    }
    int lane = tid & 31;
    if (bid < 464) {
        int w = (bid - 80) * 8 + (tid >> 5);
        if (w < 2048) {
            // node u[h][p] = R[p]·y[h] + WT4n[p]·z[h]
            int h = w >> 9, p = w & 511;
            const float* Rrow = g_Rn + (size_t)p * 512;
            const float* yh = g_yn + h * 512;
            float acc = 0.f;
#pragma unroll
            for (int r = 0; r < 4; r++) {
                float4 rv = *reinterpret_cast<const float4*>(&Rrow[r*128 + lane*4]);
                float4 yv = *reinterpret_cast<const float4*>(&yh[r*128 + lane*4]);
                acc += rv.x*yv.x + rv.y*yv.y + rv.z*yv.z + rv.w*yv.w;
            }
            float ks0 = g_ksn[h*4+0], ks1 = g_ksn[h*4+1], ks2 = g_ksn[h*4+2], ks3 = g_ksn[h*4+3];
            float4 b0 = *reinterpret_cast<const float4*>(&nqb[0*FN + lane*4]);
            float4 b1 = *reinterpret_cast<const float4*>(&nqb[1*FN + lane*4]);
            float4 b2 = *reinterpret_cast<const float4*>(&nqb[2*FN + lane*4]);
            float4 b3 = *reinterpret_cast<const float4*>(&nqb[3*FN + lane*4]);
            float4 z;
            z.x = ks0*b0.x + ks1*b1.x + ks2*b2.x + ks3*b3.x;
            z.y = ks0*b0.y + ks1*b1.y + ks2*b2.y + ks3*b3.y;
            z.z = ks0*b0.z + ks1*b1.z + ks2*b2.z + ks3*b3.z;
            z.w = ks0*b0.w + ks1*b1.w + ks2*b2.w + ks3*b3.w;
            float4 wt = *reinterpret_cast<const float4*>(&g_WT4n[p*FN + lane*4]);
            acc += wt.x*z.x + wt.y*z.y + wt.z*z.z + wt.w*z.w;
            acc = wredsum(acc);
            if (lane == 0) g_un[h*512 + p] = acc;
        } else {
            int w2 = w - 2048;
            int h = w2 >> 8, p = w2 & 255;
            const float* Rrow = g_Re + (size_t)p * 256;
            const float* yh = g_ye + h * 256;
            float acc = 0.f;
#pragma unroll
            for (int r = 0; r < 2; r++) {
                float4 rv = *reinterpret_cast<const float4*>(&Rrow[r*128 + lane*4]);
                float4 yv = *reinterpret_cast<const float4*>(&yh[r*128 + lane*4]);
                acc += rv.x*yv.x + rv.y*yv.y + rv.z*yv.z + rv.w*yv.w;
            }
            float ks0 = g_kse[h*4+0], ks1 = g_kse[h*4+1], ks2 = g_kse[h*4+2], ks3 = g_kse[h*4+3];
            float2 b0 = *reinterpret_cast<const float2*>(&eqb[0*FE + lane*2]);
            float2 b1 = *reinterpret_cast<const float2*>(&eqb[1*FE + lane*2]);
            float2 b2 = *reinterpret_cast<const float2*>(&eqb[2*FE + lane*2]);
            float2 b3 = *reinterpret_cast<const float2*>(&eqb[3*FE + lane*2]);
            float2 z;
            z.x = ks0*b0.x + ks1*b1.x + ks2*b2.x + ks3*b3.x;
            z.y = ks0*b0.y + ks1*b1.y + ks2*b2.y + ks3*b3.y;
            float2 wt = *reinterpret_cast<const float2*>(&g_WT4e[p*FE + lane*2]);
            acc += wt.x*z.x + wt.y*z.y;
            acc = wredsum(acc);
            if (lane == 0) g_ue[h*256 + p] = acc;
        }
    } else {
        // c warps: 32 total (16 node, 16 edge)
        int w = (bid - 464) * 8 + (tid >> 5);
        if (w < 16) {
            int h = w >> 2, bq = w & 3;
            const float* Srow = g_Sn + bq * 512;
            const float* yh = g_yn + h * 512;
            float acc = 0.f;
#pragma unroll
            for (int r = 0; r < 4; r++) {
                float4 sv = *reinterpret_cast<const float4*>(&Srow[r*128 + lane*4]);
                float4 yv = *reinterpret_cast<const float4*>(&yh[r*128 + lane*4]);
                acc += sv.x*yv.x + sv.y*yv.y + sv.z*yv.z + sv.w*yv.w;
            }
            float ks0 = g_ksn[h*4+0], ks1 = g_ksn[h*4+1], ks2 = g_ksn[h*4+2], ks3 = g_ksn[h*4+3];
            float4 b0 = *reinterpret_cast<const float4*>(&nqb[0*FN + lane*4]);
            float4 b1 = *reinterpret_cast<const float4*>(&nqb[1*FN + lane*4]);
            float4 b2 = *reinterpret_cast<const float4*>(&nqb[2*FN + lane*4]);
            float4 b3 = *reinterpret_cast<const float4*>(&nqb[3*FN + lane*4]);
            float4 z;
            z.x = ks0*b0.x + ks1*b1.x + ks2*b2.x + ks3*b3.x;
            z.y = ks0*b0.y + ks1*b1.y + ks2*b2.y + ks3*b3.y;
            z.z = ks0*b0.z + ks1*b1.z + ks2*b2.z + ks3*b3.z;
            z.w = ks0*b0.w + ks1*b1.w + ks2*b2.w + ks3*b3.w;
            float4 bb = *reinterpret_cast<const float4*>(&nqb[bq*FN + lane*4]);
            acc += bb.x*z.x + bb.y*z.y + bb.z*z.z + bb.w*z.w;
            acc = wredsum(acc);
            if (lane == 0) g_cn[h*4 + bq] = acc;
        } else if (w < 32) {
            int w2 = w - 16;
            int h = w2 >> 2, bq = w2 & 3;
            const float* Srow = g_Se + bq * 256;
            const float* yh = g_ye + h * 256;
            float acc = 0.f;
#pragma unroll
            for (int r = 0; r < 2; r++) {
                float4 sv = *reinterpret_cast<const float4*>(&Srow[r*128 + lane*4]);
                float4 yv = *reinterpret_cast<const float4*>(&yh[r*128 + lane*4]);
                acc += sv.x*yv.x + sv.y*yv.y + sv.z*yv.z + sv.w*yv.w;
            }
            float ks0 = g_kse[h*4+0], ks1 = g_kse[h*4+1], ks2 = g_kse[h*4+2], ks3 = g_kse[h*4+3];
            float2 b0 = *reinterpret_cast<const float2*>(&eqb[0*FE + lane*2]);
            float2 b1 = *reinterpret_cast<const float2*>(&eqb[1*FE + lane*2]);
            float2 b2 = *reinterpret_cast<const float2*>(&eqb[2*FE + lane*2]);
            float2 b3 = *reinterpret_cast<const float2*>(&eqb[3*FE + lane*2]);
            float2 z;
            z.x = ks0*b0.x + ks1*b1.x + ks2*b2.x + ks3*b3.x;
            z.y = ks0*b0.y + ks1*b1.y + ks2*b2.y + ks3*b3.y;
            float2 bb = *reinterpret_cast<const float2*>(&eqb[bq*FE + lane*2]);
            acc += bb.x*z.x + bb.y*z.y;
            acc = wredsum(acc);
            if (lane == 0) g_ce[h*4 + bq] = acc;
        }
    }
}

// ---------------- W4: raw scores s[h, 4a+b] = X[row].u[h][b] + c[h][b] ----------------
__global__ __launch_bounds__(256)
void scores_kernel(const float* __restrict__ node_in, const float* __restrict__ edge_in)
{
    int w = blockIdx.x * 8 + (threadIdx.x >> 5);
    int lane = threadIdx.x & 31;
    if (w < NH*NN) {
        int h = w >> 10, m = w & (NN - 1);
        int a = m >> 2, b = m & 3;
        int row = h * 256 + a;
        float4 uv = *reinterpret_cast<const float4*>(&g_un[h*512 + b*FN + lane*4]);
        float4 xv = *reinterpret_cast<const float4*>(&node_in[row*FN + lane*4]);
        float d = xv.x*uv.x + xv.y*uv.y + xv.z*uv.z + xv.w*uv.w;
        d = wredsum(d);
        if (lane == 0) g_nsa[h*NN + m] = d + g_cn[h*4+b];
    } else {
        int w2 = w - NH*NN;
        int h = w2 >> 12, m = w2 & (EE - 1);
        int a = m >> 2, b = m & 3;
        int row = h * 1024 + a;
        float2 uv = *reinterpret_cast<const float2*>(&g_ue[h*256 + b*FE + lane*2]);
        float2 xv = *reinterpret_cast<const float2*>(&edge_in[row*FE + lane*2]);
        float d = xv.x*uv.x + xv.y*uv.y;
        d = wredsum(d);
        if (lane == 0) g_esa[h*EE + m] = d + g_ce[h*4+b];
    }
}

// ---------------- W5: per-head softmax normalize (in place) ----------------
__global__ __launch_bounds__(1024)
void softmax_kernel()
{
    __shared__ float red[32];
    __shared__ float bc_max, bc_sum;
    int bid = blockIdx.x, tid = threadIdx.x;
    int warp = tid >> 5, lane = tid & 31;
    float* buf; int cnt;
    if (bid < 4) { buf = g_nsa + bid * NN;       cnt = 1; }
    else         { buf = g_esa + (bid - 4) * EE; cnt = 4; }

    float v[4];
    float m = -1e30f;
    for (int j = 0; j < cnt; j++) { v[j] = buf[tid + j*1024]; m = fmaxf(m, v[j]); }
#pragma unroll
    for (int o = 16; o; o >>= 1) m = fmaxf(m, __shfl_xor_sync(0xffffffffu, m, o));
    if (lane == 0) red[warp] = m;
    __syncthreads();
    if (tid == 0) {
        float x = red[0];
        for (int w = 1; w < 32; w++) x = fmaxf(x, red[w]);
        bc_max = x;
    }
    __syncthreads();
    float mx = bc_max;

    float sum = 0.f;
    for (int j = 0; j < cnt; j++) { v[j] = expf(v[j] - mx); sum += v[j]; }
#pragma unroll
    for (int o = 16; o; o >>= 1) sum += __shfl_xor_sync(0xffffffffu, sum, o);
    __syncthreads();
    if (lane == 0) red[warp] = sum;
    __syncthreads();
    if (tid == 0) {
        float x = 0.f;
        for (int w = 0; w < 32; w++) x += red[w];
        bc_sum = x;
    }
    __syncthreads();
    float inv = 1.f / bc_sum;
    for (int j = 0; j < cnt; j++) buf[tid + j*1024] = v[j] * inv;
}

// ---------------- W6: merged outputs + cleanup ----------------
// grid 2064 x 128: [0,1024) node (4 rows/blk), [1024,2048) edge (16 rows/blk), [2048,2064) cleanup
__global__ __launch_bounds__(128)
void out_kernel(const int* __restrict__ dst, const int* __restrict__ lg_dst,
                const float* __restrict__ ncb, const float* __restrict__ ecb,
                float* __restrict__ out)
{
    int bid = blockIdx.x, tid = threadIdx.x;
    if (bid < 1024) {
        __shared__ float agg[4][FN];
        int h = bid >> 8;
        int i0 = (bid & 255) * 4;
#pragma unroll
        for (int r = 0; r < 4; r++) {
            int i = i0 + r;
            int s0 = g_off_n[i], s1 = g_off_n[i + 1];
            float acc = 0.f;
            for (int p = s0; p < s1; p++) {
                int e = g_lst_n[p];
                int d = dst[e];
                bool win = true;
                for (int p2 = s0; p2 < s1; p2++) {
                    int e2 = g_lst_n[p2];
                    if (e2 > e && dst[e2] == d) win = false;   // last write wins
                }
                if (win) acc += g_esa[h*EE + e] * g_nv[h*(NN*FN) + d*FN + tid];
            }
            agg[r][tid] = acc;
        }
        __syncthreads();
        float b = ncb[tid];
        float a0 = b, a1 = b, a2 = b, a3 = b;
#pragma unroll 4
        for (int f = 0; f < FN; f++) {
            float w = g_ncWT[f*FNO + tid];
            a0 += agg[0][f] * w;
            a1 += agg[1][f] * w;
            a2 += agg[2][f] * w;
            a3 += agg[3][f] * w;
        }
        float* o = out + h*(NN*FNO) + i0*FNO + tid;
        o[0*FNO] = fmaxf(a0, 0.f);
        o[1*FNO] = fmaxf(a1, 0.f);
        o[2*FNO] = fmaxf(a2, 0.f);
        o[3*FNO] = fmaxf(a3, 0.f);
    } else if (bid < 2048) {
        __shared__ float agg[16][FEO];
        int b = bid - 1024;
        int h = b >> 8;
        int i0 = (b & 255) * 16;
        int col = tid & 63, rg = tid >> 6;
#pragma unroll
        for (int k = 0; k < 8; k++) {
            int lr = rg * 8 + k;
            int i = i0 + lr;
            int s0 = g_off_e[i], s1 = g_off_e[i + 1];
            float acc = 0.f;
            for (int p = s0; p < s1; p++) {
                int l = g_lst_e[p];
                int ld = lg_dst[l];
                bool win = true;
                for (int p2 = s0; p2 < s1; p2++) {
                    int l2 = g_lst_e[p2];
                    if (l2 > l && lg_dst[l2] == ld) win = false;
                }
                if (win) acc += g_ev[h*(EE*FE) + ld*FE + col];
            }
            acc *= g_nsa[h*NN + dst[i]];
            agg[lr][col] = acc;
        }
        __syncthreads();
        float a[8];
        float bb = ecb[col];
#pragma unroll
        for (int k = 0; k < 8; k++) a[k] = bb;
#pragma unroll 4
        for (int f = 0; f < FE; f++) {
            float w = g_ecWT[f*FEO + col];
#pragma unroll
            for (int k = 0; k < 8; k++) a[k] += agg[rg*8 + k][f] * w;
        }
#pragma unroll
        for (int k = 0; k < 8; k++) {
            int i = i0 + rg*8 + k;
            out[NODE_OUT_SZ + h*(EE*FEO) + i*FEO + col] = fmaxf(a[k], 0.f);
        }
    } else {
        // cleanup for next run
        int idx = (bid - 2048) * 128 + tid;       // 0..2047
        for (int i = idx; i < NN; i += 2048) { g_cnt_n[i] = 0; g_fc_n[i] = 0; }
        for (int i = idx; i < EE; i += 2048) { g_cnt_e[i] = 0; g_fc_e[i] = 0; }
        for (int i = idx; i < NH*512; i += 2048) g_yn[i] = 0.f;
        for (int i = idx; i < NH*256; i += 2048) g_ye[i] = 0.f;
        if (idx < NH*4) { g_ksn[idx] = 0.f; g_kse[idx] = 0.f; }
    }
}

// ---------------- launcher ----------------
extern "C" void kernel_launch(void* const* d_in, const int* in_sizes, int n_in,
                              void* d_out, int out_size)
{
    const float* node_inputs = (const float*)d_in[0];
    const float* edge_inputs = (const float*)d_in[1];
    const int*   src         = (const int*)d_in[2];
    const int*   dst         = (const int*)d_in[3];
    const int*   lg_src      = (const int*)d_in[4];
    const int*   lg_dst      = (const int*)d_in[5];
    const float* nqW = (const float*)d_in[6];
    const float* nqb = (const float*)d_in[7];
    const float* nkW = (const float*)d_in[8];
    const float* nkb = (const float*)d_in[9];
    const float* nvW = (const float*)d_in[10];
    const float* nvb = (const float*)d_in[11];
    const float* eqW = (const float*)d_in[12];
    const float* eqb = (const float*)d_in[13];
    const float* ekW = (const float*)d_in[14];
    const float* ekb = (const float*)d_in[15];
    const float* evW = (const float*)d_in[16];
    const float* evb = (const float*)d_in[17];
    const float* ncW = (const float*)d_in[18];
    const float* ncb = (const float*)d_in[19];
    const float* ecW = (const float*)d_in[20];
    const float* ecb = (const float*)d_in[21];
    float* out = (float*)d_out;

    prep_kernel<<<1504, 256>>>(node_inputs, edge_inputs, nkW, nkb, ekW, ekb,
                               src, lg_src, ncW, ecW, nqW, eqW,
                               nvW, nvb, evW, evb);
    scan_y_gram_kernel<<<626, 256>>>(node_inputs, edge_inputs, nqb, eqb);
    fill_uc_kernel<<<468, 256>>>(src, lg_src, nqb, eqb);
    scores_kernel<<<2560, 256>>>(node_inputs, edge_inputs);
    softmax_kernel<<<8, 1024>>>();
    out_kernel<<<2064, 128>>>(dst, lg_dst, ncb, ecb, out);
}